// round 14
// baseline (speedup 1.0000x reference)
#include <cuda_runtime.h>
#include <cuda_bf16.h>
#include <math.h>
#include <cstdint>

#define BATCH 8
#define NTOK 4096
#define DI 512
#define HH 64
#define SROWC 65   // padded row stride in COMPLEX (float2) units

// ---------------- device scratch (static: no allocations allowed) ----------------
__device__ float g_part[BATCH * 8 * DI];
__device__ float g_pooled[BATCH * DI];
__device__ float g_dtg[BATCH * DI];
__device__ __nv_bfloat16 g_Ath[(size_t)BATCH * 2 * DI * NTOK];     // [B][k=1024][n=4096] bf16 hi
__device__ __nv_bfloat16 g_Atl[(size_t)BATCH * 2 * DI * NTOK];     // [B][k=1024][n=4096] bf16 lo
__device__ __nv_bfloat16 g_Wh[DI * 2 * DI];                        // [o][k] bf16 hi
__device__ __nv_bfloat16 g_Wl[DI * 2 * DI];                        // [o][k] bf16 lo

// ---------------- pooled mean ------------------------------------------------------
__global__ void pooled_partial_kernel(const float* __restrict__ x) {
    int b = blockIdx.x, s = blockIdx.y, d = threadIdx.x;
    const float* p = x + ((size_t)b * NTOK + (size_t)s * 512) * DI + d;
    float acc = 0.f;
#pragma unroll 8
    for (int n = 0; n < 512; n++) acc += p[(size_t)n * DI];
    g_part[(b * 8 + s) * DI + d] = acc;
}
__global__ void pooled_combine_kernel() {
    int b = blockIdx.x, d = threadIdx.x;
    float acc = 0.f;
#pragma unroll
    for (int s = 0; s < 8; s++) acc += g_part[(b * 8 + s) * DI + d];
    g_pooled[b * DI + d] = acc * (1.0f / (float)NTOK);
}

// ---------------- gamma -----------------------------------------------------------
__global__ void gamma_kernel(const float* __restrict__ Wg,
                             const float* __restrict__ bg,
                             const float* __restrict__ log_base,
                             const int* __restrict__ ks) {
    int b = blockIdx.x;
    int warp = threadIdx.x >> 5, lane = threadIdx.x & 31;
    int d = blockIdx.y * 8 + warp;
    const float* wr = Wg + (size_t)d * DI;
    const float* pl = g_pooled + b * DI;
    float acc = 0.f;
    for (int k = lane; k < DI; k += 32) acc += wr[k] * pl[k];
#pragma unroll
    for (int o = 16; o; o >>= 1) acc += __shfl_xor_sync(0xffffffffu, acc, o);
    if (lane == 0) {
        float z = acc + bg[d] + log_base[d];
        float sp = (z > 20.f) ? z : log1pf(expf(z));
        float gm = fminf(sp, 0.35f);
        int k = ks[0]; if (k < 1) k = 1;
        g_dtg[b * DI + d] = gm / (float)k;
    }
}

// ---------------- exact reaction update -------------------------------------------
__device__ __forceinline__ void react_pt(float& re, float& im,
                                         float a, float b2, float ea, float dt, int azero) {
    float q = re * re + im * im;
    float qn;
    if (azero) {
        qn = q / (1.f + b2 * q * dt);
    } else {
        float den = fmaxf(b2 * q + (a - b2 * q) * ea, 1e-8f);
        qn = fmaxf(a * q / den, 0.f);
    }
    float sc = sqrtf(qn / fmaxf(q, 1e-8f));
    re *= sc; im *= sc;
}

// ---------------- 8-point DFT on float2 (DIF, bit-reversed output slots) ----------
template <int SGN>
__device__ __forceinline__ void dft8f2(float2* v) {
    const float INV = 0.70710678118654752f;
    const float S = (float)SGN;
#pragma unroll
    for (int j = 0; j < 4; j++) {
        float2 a = v[j], b = v[j + 4];
        float sr = a.x + b.x, si = a.y + b.y;
        float tr = a.x - b.x, ti = a.y - b.y;
        float orr, oii;
        if (j == 0)      { orr = tr;                    oii = ti; }
        else if (j == 1) { orr = INV * (tr - S * ti);   oii = INV * (S * tr + ti); }
        else if (j == 2) { orr = -S * ti;               oii = S * tr; }
        else             { orr = -INV * (tr + S * ti);  oii = INV * (S * tr - ti); }
        v[j] = make_float2(sr, si);
        v[j + 4] = make_float2(orr, oii);
    }
#pragma unroll
    for (int gb = 0; gb < 8; gb += 4) {
        { float2 a = v[gb], b = v[gb + 2];
          v[gb] = make_float2(a.x + b.x, a.y + b.y);
          v[gb + 2] = make_float2(a.x - b.x, a.y - b.y); }
        { float2 a = v[gb + 1], b = v[gb + 3];
          float tr = a.x - b.x, ti = a.y - b.y;
          v[gb + 1] = make_float2(a.x + b.x, a.y + b.y);
          v[gb + 3] = make_float2(-S * ti, S * tr); }
    }
#pragma unroll
    for (int p = 0; p < 8; p += 2) {
        float2 a = v[p], b = v[p + 1];
        v[p] = make_float2(a.x + b.x, a.y + b.y);
        v[p + 1] = make_float2(a.x - b.x, a.y - b.y);
    }
}

// One 8-wide sub-pass of a 64-pt FFT along a line, with fused boundary ops.
// LM: 0 = tile, 1 = tile + reaction, 2 = global x (imag=0) + reaction
// SM: 0 = tile, 1 = tile + spectral phase (incl 1/4096),
//     3 = reaction + bf16 hi/lo split + global store ([k][n] layout, coalesced in n)
template <int SGN, bool TW, int JS, int GS, int LM, int SM>
__device__ __forceinline__ void pass8x(
    float2* __restrict__ tile, const float2* __restrict__ tw,
    int base, int stride, int g, int aux,
    float ra, float rb2, float rea, float rdt, int razero,
    const float2* __restrict__ py,
    const float* __restrict__ gx,
    __nv_bfloat16* __restrict__ bHr, __nv_bfloat16* __restrict__ bHi,
    __nv_bfloat16* __restrict__ bLr, __nv_bfloat16* __restrict__ bLi)
{
    const int BR[8] = {0, 4, 2, 6, 1, 5, 3, 7};
    float2 v[8];
#pragma unroll
    for (int j = 0; j < 8; j++) {
        int e = j * JS + g * GS;
        if (LM == 2) {
            v[j] = make_float2(gx[(size_t)(aux * 64 + e) * DI], 0.f);
        } else {
            v[j] = tile[base + e * stride];
        }
        if (LM >= 1) react_pt(v[j].x, v[j].y, ra, rb2, rea, rdt, razero);
    }
    dft8f2<SGN>(v);
    float2 px = make_float2(0.f, 0.f);
    if (SM == 1) px = py[aux];
#pragma unroll
    for (int q = 0; q < 8; q++) {
        float2 y = v[BR[q]];
        if (TW) {
            int m = (g * q) & 63;
            float2 w = tw[m];
            float s = (SGN < 0) ? -w.y : w.y;
            float t = y.x * w.x - y.y * s;
            y.y = y.x * s + y.y * w.x;
            y.x = t;
        }
        int e = q * JS + g * GS;
        if (SM == 1) {
            float2 pe = py[e];
            float pc = (pe.x * px.x - pe.y * px.y) * (1.f / 4096.f);
            float ps = (pe.x * px.y + pe.y * px.x) * (1.f / 4096.f);
            float t = y.x * pc - y.y * ps;
            y.y = y.x * ps + y.y * pc;
            y.x = t;
        }
        if (SM == 3) {
            react_pt(y.x, y.y, ra, rb2, rea, rdt, razero);
            int lin = e * 64 + aux;       // token index, coalesced over aux within warp
            __nv_bfloat16 hr = __float2bfloat16(y.x);
            __nv_bfloat16 hi = __float2bfloat16(y.y);
            bHr[lin] = hr;
            bHi[lin] = hi;
            bLr[lin] = __float2bfloat16(y.x - __bfloat162float(hr));
            bLi[lin] = __float2bfloat16(y.y - __bfloat162float(hi));
        } else {
            tile[base + e * stride] = y;
        }
    }
}

// ---------------- main per-plane diffusion kernel ---------------------------------
__global__ __launch_bounds__(256, 4) void fft_kernel(const float* __restrict__ x,
                                                     const float* __restrict__ alpha_raw,
                                                     const float* __restrict__ beta_raw,
                                                     const int* __restrict__ ks) {
    __shared__ float2 tile[HH * SROWC];
    __shared__ float2 tw[64], py[64];
    __shared__ float sh_par[6];
    __shared__ int sh_k;

    int tid = threadIdx.x;
    int plane = blockIdx.x;
    int b = plane >> 9;
    int c = plane & (DI - 1);

    if (tid < 64) {
        float ang = 6.283185307179586f * (float)tid / 64.f;
        tw[tid] = make_float2(cosf(ang), sinf(ang));
        int kr = ((tid & 7) << 3) | (tid >> 3);   // storage index -> frequency
        float e = 2.f * cosf(6.283185307179586f * (float)kr / 64.f) - 2.f;
        float dtg = g_dtg[b * DI + c];
        float arg = dtg * e;
        py[tid] = make_float2(cosf(arg), sinf(arg));
    }
    if (tid == 0) {
        int k = ks[0]; if (k < 1) k = 1;
        sh_k = k;
        float dt = 1.f / (float)k;
        float al = 0.25f * tanhf(alpha_raw[c]);
        float br = beta_raw[c];
        float sp = (br > 20.f) ? br : log1pf(expf(br));
        float a = 2.f * al;
        float b2 = 2.f * (sp + 1e-4f);
        sh_par[0] = a;
        sh_par[1] = b2;
        sh_par[2] = expf(-a * 0.5f * dt);
        sh_par[3] = 0.5f * dt;
        sh_par[4] = expf(-a * dt);
        sh_par[5] = dt;
    }
    __syncthreads();

    float a = sh_par[0], b2 = sh_par[1];
    float ea_h = sh_par[2], hdt = sh_par[3];
    float ea_f = sh_par[4], fdt = sh_par[5];
    int ksteps = sh_k;
    int azero = fabsf(a) < 1e-6f;

    const float* xp = x + (size_t)b * NTOK * DI + c;
    __nv_bfloat16* bHr = g_Ath + ((size_t)b * 1024 + c) * NTOK;        // hi real (k=c)
    __nv_bfloat16* bHi = g_Ath + ((size_t)b * 1024 + DI + c) * NTOK;   // hi imag (k=512+c)
    __nv_bfloat16* bLr = g_Atl + ((size_t)b * 1024 + c) * NTOK;
    __nv_bfloat16* bLi = g_Atl + ((size_t)b * 1024 + DI + c) * NTOK;

#define FORALL(body)                         \
    {                                        \
        _Pragma("unroll")                    \
        for (int it = 0; it < 2; it++) {     \
            int t = tid + it * 256;          \
            int ln = t & 63, g = t >> 6;     \
            (void)ln; (void)g;               \
            body;                            \
        }                                    \
    }

    for (int step = 0; step < ksteps; step++) {
        if (step == 0) {
            FORALL((pass8x<-1, true, 8, 1, 2, 0>(tile, tw, ln * SROWC, 1, g, ln,
                                                 a, b2, ea_h, hdt, azero, py, xp,
                                                 bHr, bHi, bLr, bLi)));
        } else {
            FORALL((pass8x<-1, true, 8, 1, 1, 0>(tile, tw, ln * SROWC, 1, g, ln,
                                                 a, b2, ea_f, fdt, azero, py, xp,
                                                 bHr, bHi, bLr, bLi)));
        }
        __syncthreads();
        FORALL((pass8x<-1, false, 1, 8, 0, 0>(tile, tw, ln * SROWC, 1, g, 0,
                                              0.f, 0.f, 0.f, 0.f, 0, py, xp,
                                              bHr, bHi, bLr, bLi)));   // fwd rows s2
        __syncthreads();
        FORALL((pass8x<-1, true, 8, 1, 0, 0>(tile, tw, ln, SROWC, g, 0,
                                             0.f, 0.f, 0.f, 0.f, 0, py, xp,
                                             bHr, bHi, bLr, bLi)));    // fwd cols s1
        __syncthreads();
        FORALL((pass8x<-1, false, 1, 8, 0, 1>(tile, tw, ln, SROWC, g, ln,
                                              0.f, 0.f, 0.f, 0.f, 0, py, xp,
                                              bHr, bHi, bLr, bLi)));   // fwd cols s2 + phase
        __syncthreads();
        FORALL((pass8x<1, true, 1, 8, 0, 0>(tile, tw, ln * SROWC, 1, g, 0,
                                            0.f, 0.f, 0.f, 0.f, 0, py, xp,
                                            bHr, bHi, bLr, bLi)));     // inv rows s1
        __syncthreads();
        FORALL((pass8x<1, false, 8, 1, 0, 0>(tile, tw, ln * SROWC, 1, g, 0,
                                             0.f, 0.f, 0.f, 0.f, 0, py, xp,
                                             bHr, bHi, bLr, bLi)));    // inv rows s2
        __syncthreads();
        FORALL((pass8x<1, true, 1, 8, 0, 0>(tile, tw, ln, SROWC, g, 0,
                                            0.f, 0.f, 0.f, 0.f, 0, py, xp,
                                            bHr, bHi, bLr, bLi)));     // inv cols s1
        __syncthreads();
        if (step == ksteps - 1) {
            FORALL((pass8x<1, false, 8, 1, 0, 3>(tile, tw, ln, SROWC, g, ln,
                                                 a, b2, ea_h, hdt, azero, py, xp,
                                                 bHr, bHi, bLr, bLi)));
        } else {
            FORALL((pass8x<1, false, 8, 1, 0, 0>(tile, tw, ln, SROWC, g, 0,
                                                 0.f, 0.f, 0.f, 0.f, 0, py, xp,
                                                 bHr, bHi, bLr, bLi)));
            __syncthreads();
        }
    }
#undef FORALL
}

// ---------------- Wout fp32 -> bf16 hi/lo -----------------------------------------
__global__ void wconv_kernel(const float* __restrict__ Wout) {
    int i = blockIdx.x * blockDim.x + threadIdx.x;
    if (i < DI * 2 * DI) {
        float v = Wout[i];
        __nv_bfloat16 h = __float2bfloat16(v);
        g_Wh[i] = h;
        g_Wl[i] = __float2bfloat16(v - __bfloat162float(h));
    }
}

// ================= mma.sync bf16 GEMM =============================================
// out[b,n,o] = sum_k A[b,n,k] * W[o,k] + x*Dp, via Ah*Wh + Ah*Wl + Al*Wh.
// A stored K-major [b][k][n]; A tiles [k=64][n=128] fed via ldmatrix.trans.
// CTA tile: M=128 (n) x N=128 (o), K chunks of 64. 8 warps 4x2, warp tile 32x64.
#define BK 64
#define AH_OFF 0
#define AL_OFF 16384
#define WH_OFF 32768
#define WL_OFF 49152
#define STAGE_B 65536

__device__ __forceinline__ uint32_t smem_u32(const void* p) {
    uint32_t a;
    asm("{ .reg .u64 t; cvta.to.shared.u64 t, %1; cvt.u32.u64 %0, t; }" : "=r"(a) : "l"(p));
    return a;
}
__device__ __forceinline__ void cp16(uint32_t dst, const void* src) {
    asm volatile("cp.async.cg.shared.global [%0], [%1], 16;" :: "r"(dst), "l"(src));
}
__device__ __forceinline__ void ldsm4(uint32_t* r, uint32_t addr) {
    asm volatile("ldmatrix.sync.aligned.m8n8.x4.shared.b16 {%0,%1,%2,%3}, [%4];"
                 : "=r"(r[0]), "=r"(r[1]), "=r"(r[2]), "=r"(r[3]) : "r"(addr));
}
__device__ __forceinline__ void ldsm4t(uint32_t* r, uint32_t addr) {
    asm volatile("ldmatrix.sync.aligned.m8n8.x4.trans.shared.b16 {%0,%1,%2,%3}, [%4];"
                 : "=r"(r[0]), "=r"(r[1]), "=r"(r[2]), "=r"(r[3]) : "r"(addr));
}
__device__ __forceinline__ void mma16816(float* c, const uint32_t* a, uint32_t b0, uint32_t b1) {
    asm volatile("mma.sync.aligned.m16n8k16.row.col.f32.bf16.bf16.f32 "
                 "{%0,%1,%2,%3}, {%4,%5,%6,%7}, {%8,%9}, {%0,%1,%2,%3};"
                 : "+f"(c[0]), "+f"(c[1]), "+f"(c[2]), "+f"(c[3])
                 : "r"(a[0]), "r"(a[1]), "r"(a[2]), "r"(a[3]), "r"(b0), "r"(b1));
}
__device__ __forceinline__ uint32_t swz(uint32_t off) { return off ^ ((off >> 3) & 0x70); }

__global__ __launch_bounds__(256) void mma_gemm_kernel(const float* __restrict__ x,
                                                       const float* __restrict__ Dp,
                                                       float* __restrict__ out) {
    extern __shared__ char dsmem_raw[];
    uint32_t raw = smem_u32(dsmem_raw);
    uint32_t base = (raw + 1023u) & ~1023u;

    int tid = threadIdx.x;
    int wid = tid >> 5, lid = tid & 31;
    int wm = wid >> 1, wn = wid & 1;          // warp grid 4 (M/n) x 2 (N/o, 64 each)
    int n0 = blockIdx.x * 128;
    int o0 = blockIdx.y * 128;
    int b = blockIdx.z;

    const __nv_bfloat16* gAh = g_Ath + (size_t)b * 1024 * NTOK + n0;   // [k][n], + n0
    const __nv_bfloat16* gAl = g_Atl + (size_t)b * 1024 * NTOK + n0;
    const __nv_bfloat16* gWh = g_Wh + (size_t)o0 * 1024;
    const __nv_bfloat16* gWl = g_Wl + (size_t)o0 * 1024;

    // A loader: [k=64 rows][128 n] = 64 x 256B; 4 threads/row, 4 x 16B per thread
    int rowA = tid >> 2, q4 = tid & 3;
    // W loader: [o=128 rows][64 k] = 128 x 128B; 2 threads/row, 4 x 16B per thread
    int rw = tid >> 1, qw = tid & 1;

#define ISSUE_CHUNK(kc0, stg)                                                              \
    {                                                                                      \
        uint32_t sb = base + (uint32_t)(stg) * STAGE_B;                                    \
        _Pragma("unroll")                                                                  \
        for (int i = 0; i < 4; i++) {                                                      \
            int n16 = q4 + i * 4;                                                          \
            uint32_t so = (uint32_t)(rowA * 256 + ((n16 ^ (rowA & 7)) * 16));              \
            cp16(sb + AH_OFF + so, gAh + (size_t)((kc0) + rowA) * NTOK + n16 * 8);         \
            cp16(sb + AL_OFF + so, gAl + (size_t)((kc0) + rowA) * NTOK + n16 * 8);         \
        }                                                                                  \
        _Pragma("unroll")                                                                  \
        for (int i = 0; i < 4; i++) {                                                      \
            int c16 = qw * 4 + i;                                                          \
            uint32_t so = swz((uint32_t)(rw * 128 + c16 * 16));                            \
            cp16(sb + WH_OFF + so, gWh + (size_t)rw * 1024 + (kc0) + c16 * 8);             \
            cp16(sb + WL_OFF + so, gWl + (size_t)rw * 1024 + (kc0) + c16 * 8);             \
        }                                                                                  \
        asm volatile("cp.async.commit_group;");                                            \
    }

    float acc[2][8][4];
#pragma unroll
    for (int m = 0; m < 2; m++)
#pragma unroll
        for (int nf = 0; nf < 8; nf++)
#pragma unroll
            for (int r = 0; r < 4; r++) acc[m][nf][r] = 0.f;

    ISSUE_CHUNK(0, 0);
    asm volatile("cp.async.wait_group 0;" ::: "memory");
    __syncthreads();

    int sub = lid >> 3, l7 = lid & 7;
    // A fragment (trans) addressing
    int aklane = (sub >> 1) * 8 + l7;
    // W fragment addressing (row-major [o][k], non-trans)
    int wrow_b = wn * 64 + (sub >> 1) * 8 + l7;
    int wkb_b = (sub & 1) * 16;

    for (int ch = 0; ch < 16; ch++) {
        int stg = ch & 1;
        if (ch + 1 < 16) ISSUE_CHUNK((ch + 1) * BK, stg ^ 1);

        uint32_t sb = base + (uint32_t)stg * STAGE_B;
#pragma unroll
        for (int kk = 0; kk < 4; kk++) {
            uint32_t ah[2][4], al[2][4], wh[4][4], wl[4][4];
#pragma unroll
            for (int m = 0; m < 2; m++) {
                int n16 = (wm * 32 + m * 16 + (sub & 1) * 8) >> 3;
                uint32_t off = (uint32_t)((kk * 16 + aklane) * 256 + ((n16 ^ l7) * 16));
                ldsm4t(ah[m], sb + AH_OFF + off);
                ldsm4t(al[m], sb + AL_OFF + off);
            }
#pragma unroll
            for (int np = 0; np < 4; np++) {
                uint32_t off = swz((uint32_t)((wrow_b + np * 16) * 128 + kk * 32 + wkb_b));
                ldsm4(wh[np], sb + WH_OFF + off);
                ldsm4(wl[np], sb + WL_OFF + off);
            }
#pragma unroll
            for (int m = 0; m < 2; m++)
#pragma unroll
                for (int nf = 0; nf < 8; nf++) {
                    uint32_t bh0 = wh[nf >> 1][(nf & 1) * 2], bh1 = wh[nf >> 1][(nf & 1) * 2 + 1];
                    uint32_t bl0 = wl[nf >> 1][(nf & 1) * 2], bl1 = wl[nf >> 1][(nf & 1) * 2 + 1];
                    mma16816(acc[m][nf], ah[m], bh0, bh1);
                    mma16816(acc[m][nf], ah[m], bl0, bl1);
                    mma16816(acc[m][nf], al[m], bh0, bh1);
                }
        }

        if (ch + 1 < 16) {
            asm volatile("cp.async.wait_group 0;" ::: "memory");
            __syncthreads();
        }
    }
#undef ISSUE_CHUNK

    // epilogue: out = acc + x * Dp
    int g = lid >> 2, tg = lid & 3;
    float2 dv[8];
#pragma unroll
    for (int nf = 0; nf < 8; nf++)
        dv[nf] = *(const float2*)(Dp + o0 + wn * 64 + nf * 8 + tg * 2);
#pragma unroll
    for (int m = 0; m < 2; m++)
#pragma unroll
        for (int rr = 0; rr < 2; rr++) {
            int row = n0 + wm * 32 + m * 16 + g + rr * 8;
            size_t rowoff = ((size_t)b * NTOK + row) * DI;
#pragma unroll
            for (int nf = 0; nf < 8; nf++) {
                int col = o0 + wn * 64 + nf * 8 + tg * 2;
                const float2 xv = *(const float2*)(x + rowoff + col);
                float2 ov;
                ov.x = acc[m][nf][rr * 2 + 0] + xv.x * dv[nf].x;
                ov.y = acc[m][nf][rr * 2 + 1] + xv.y * dv[nf].y;
                *(float2*)(out + rowoff + col) = ov;
            }
        }
}

// ---------------- launch ----------------------------------------------------------
extern "C" void kernel_launch(void* const* d_in, const int* in_sizes, int n_in,
                              void* d_out, int out_size) {
    const float* x         = (const float*)d_in[0];
    const float* Wg        = (const float*)d_in[1];
    const float* bg        = (const float*)d_in[2];
    const float* log_base  = (const float*)d_in[3];
    const float* alpha_raw = (const float*)d_in[4];
    const float* beta_raw  = (const float*)d_in[5];
    const float* Wout      = (const float*)d_in[6];
    const float* Dp        = (const float*)d_in[7];
    const int*   ks        = (const int*)d_in[8];
    float* out = (float*)d_out;

    int dyn = 2 * STAGE_B + 1024;
    cudaFuncSetAttribute(mma_gemm_kernel, cudaFuncAttributeMaxDynamicSharedMemorySize, dyn);

    pooled_partial_kernel<<<dim3(BATCH, 8), DI>>>(x);
    pooled_combine_kernel<<<BATCH, DI>>>();
    gamma_kernel<<<dim3(BATCH, 64), 256>>>(Wg, bg, log_base, ks);
    wconv_kernel<<<(DI * 2 * DI + 255) / 256, 256>>>(Wout);
    fft_kernel<<<BATCH * DI, 256>>>(x, alpha_raw, beta_raw, ks);
    mma_gemm_kernel<<<dim3(NTOK / 128, DI / 128, BATCH), 256, dyn>>>(x, Dp, out);
}

// round 15
// speedup vs baseline: 1.0565x; 1.0565x over previous
#include <cuda_runtime.h>
#include <cuda_bf16.h>
#include <math.h>
#include <cstdint>

#define BATCH 8
#define NTOK 4096
#define DI 512
#define HH 64
#define SROWC 65   // padded row stride in COMPLEX (float2) units

// ---------------- device scratch (static: no allocations allowed) ----------------
__device__ float g_part[BATCH * 16 * DI];
__device__ float g_pooled[BATCH * DI];
__device__ float g_dtg[BATCH * DI];
__device__ __nv_bfloat16 g_Ath[(size_t)BATCH * 2 * DI * NTOK];     // [B][k=1024][n=4096] bf16 hi
__device__ __nv_bfloat16 g_Atl[(size_t)BATCH * 2 * DI * NTOK];     // [B][k=1024][n=4096] bf16 lo
__device__ __nv_bfloat16 g_Wh[DI * 2 * DI];                        // [o][k] bf16 hi
__device__ __nv_bfloat16 g_Wl[DI * 2 * DI];                        // [o][k] bf16 lo

// ---------------- pooled mean ------------------------------------------------------
__global__ void pooled_partial_kernel(const float* __restrict__ x) {
    int b = blockIdx.x, s = blockIdx.y, d = threadIdx.x;
    const float* p = x + ((size_t)b * NTOK + (size_t)s * 256) * DI + d;
    float acc = 0.f;
#pragma unroll 8
    for (int n = 0; n < 256; n++) acc += p[(size_t)n * DI];
    g_part[(b * 16 + s) * DI + d] = acc;
}
__global__ void pooled_combine_kernel() {
    int b = blockIdx.x, d = threadIdx.x;
    float acc = 0.f;
#pragma unroll
    for (int s = 0; s < 16; s++) acc += g_part[(b * 16 + s) * DI + d];
    g_pooled[b * DI + d] = acc * (1.0f / (float)NTOK);
}

// ---------------- gamma -----------------------------------------------------------
__global__ void gamma_kernel(const float* __restrict__ Wg,
                             const float* __restrict__ bg,
                             const float* __restrict__ log_base,
                             const int* __restrict__ ks) {
    int b = blockIdx.x;
    int warp = threadIdx.x >> 5, lane = threadIdx.x & 31;
    int d = blockIdx.y * 8 + warp;
    const float* wr = Wg + (size_t)d * DI;
    const float* pl = g_pooled + b * DI;
    float acc = 0.f;
    for (int k = lane; k < DI; k += 32) acc += wr[k] * pl[k];
#pragma unroll
    for (int o = 16; o; o >>= 1) acc += __shfl_xor_sync(0xffffffffu, acc, o);
    if (lane == 0) {
        float z = acc + bg[d] + log_base[d];
        float sp = (z > 20.f) ? z : log1pf(expf(z));
        float gm = fminf(sp, 0.35f);
        int k = ks[0]; if (k < 1) k = 1;
        g_dtg[b * DI + d] = gm / (float)k;
    }
}

// ---------------- exact reaction update -------------------------------------------
__device__ __forceinline__ void react_pt(float& re, float& im,
                                         float a, float b2, float ea, float dt, int azero) {
    float q = re * re + im * im;
    float qn;
    if (azero) {
        qn = q / (1.f + b2 * q * dt);
    } else {
        float den = fmaxf(b2 * q + (a - b2 * q) * ea, 1e-8f);
        qn = fmaxf(a * q / den, 0.f);
    }
    float sc = sqrtf(qn / fmaxf(q, 1e-8f));
    re *= sc; im *= sc;
}

// ---------------- 8-point DFT on float2 (DIF, bit-reversed output slots) ----------
template <int SGN>
__device__ __forceinline__ void dft8f2(float2* v) {
    const float INV = 0.70710678118654752f;
    const float S = (float)SGN;
#pragma unroll
    for (int j = 0; j < 4; j++) {
        float2 a = v[j], b = v[j + 4];
        float sr = a.x + b.x, si = a.y + b.y;
        float tr = a.x - b.x, ti = a.y - b.y;
        float orr, oii;
        if (j == 0)      { orr = tr;                    oii = ti; }
        else if (j == 1) { orr = INV * (tr - S * ti);   oii = INV * (S * tr + ti); }
        else if (j == 2) { orr = -S * ti;               oii = S * tr; }
        else             { orr = -INV * (tr + S * ti);  oii = INV * (S * tr - ti); }
        v[j] = make_float2(sr, si);
        v[j + 4] = make_float2(orr, oii);
    }
#pragma unroll
    for (int gb = 0; gb < 8; gb += 4) {
        { float2 a = v[gb], b = v[gb + 2];
          v[gb] = make_float2(a.x + b.x, a.y + b.y);
          v[gb + 2] = make_float2(a.x - b.x, a.y - b.y); }
        { float2 a = v[gb + 1], b = v[gb + 3];
          float tr = a.x - b.x, ti = a.y - b.y;
          v[gb + 1] = make_float2(a.x + b.x, a.y + b.y);
          v[gb + 3] = make_float2(-S * ti, S * tr); }
    }
#pragma unroll
    for (int p = 0; p < 8; p += 2) {
        float2 a = v[p], b = v[p + 1];
        v[p] = make_float2(a.x + b.x, a.y + b.y);
        v[p + 1] = make_float2(a.x - b.x, a.y - b.y);
    }
}

// One 8-wide sub-pass of a 64-pt FFT along a line, with fused boundary ops.
// LM: 0 = tile, 1 = tile + reaction, 2 = global x (imag=0) + reaction
// SM: 0 = tile, 1 = tile + spectral phase (incl 1/4096),
//     3 = reaction + bf16 hi/lo split + global store ([k][n] layout, coalesced in n)
template <int SGN, bool TW, int JS, int GS, int LM, int SM>
__device__ __forceinline__ void pass8x(
    float2* __restrict__ tile, const float2* __restrict__ tw,
    int base, int stride, int g, int aux,
    float ra, float rb2, float rea, float rdt, int razero,
    const float2* __restrict__ py,
    const float* __restrict__ gx,
    __nv_bfloat16* __restrict__ bHr, __nv_bfloat16* __restrict__ bHi,
    __nv_bfloat16* __restrict__ bLr, __nv_bfloat16* __restrict__ bLi)
{
    const int BR[8] = {0, 4, 2, 6, 1, 5, 3, 7};
    float2 v[8];
#pragma unroll
    for (int j = 0; j < 8; j++) {
        int e = j * JS + g * GS;
        if (LM == 2) {
            v[j] = make_float2(gx[(size_t)(aux * 64 + e) * DI], 0.f);
        } else {
            v[j] = tile[base + e * stride];
        }
        if (LM >= 1) react_pt(v[j].x, v[j].y, ra, rb2, rea, rdt, razero);
    }
    dft8f2<SGN>(v);
    float2 px = make_float2(0.f, 0.f);
    if (SM == 1) px = py[aux];
#pragma unroll
    for (int q = 0; q < 8; q++) {
        float2 y = v[BR[q]];
        if (TW) {
            int m = (g * q) & 63;
            float2 w = tw[m];
            float s = (SGN < 0) ? -w.y : w.y;
            float t = y.x * w.x - y.y * s;
            y.y = y.x * s + y.y * w.x;
            y.x = t;
        }
        int e = q * JS + g * GS;
        if (SM == 1) {
            float2 pe = py[e];
            float pc = (pe.x * px.x - pe.y * px.y) * (1.f / 4096.f);
            float ps = (pe.x * px.y + pe.y * px.x) * (1.f / 4096.f);
            float t = y.x * pc - y.y * ps;
            y.y = y.x * ps + y.y * pc;
            y.x = t;
        }
        if (SM == 3) {
            react_pt(y.x, y.y, ra, rb2, rea, rdt, razero);
            int lin = e * 64 + aux;       // token index, coalesced over aux within warp
            __nv_bfloat16 hr = __float2bfloat16(y.x);
            __nv_bfloat16 hi = __float2bfloat16(y.y);
            bHr[lin] = hr;
            bHi[lin] = hi;
            bLr[lin] = __float2bfloat16(y.x - __bfloat162float(hr));
            bLi[lin] = __float2bfloat16(y.y - __bfloat162float(hi));
        } else {
            tile[base + e * stride] = y;
        }
    }
}

// ---------------- main per-plane diffusion kernel ---------------------------------
// Half-scope barrier: lines 0-31 are processed entirely by even warps, lines 32-63
// by odd warps (worker map ln = t&63 with 256 threads x 2 iters). Within-dimension
// s1->s2 boundaries only need a 128-thread named barrier per half.
__device__ __forceinline__ void half_bar(int grp) {
    asm volatile("bar.sync %0, 128;" :: "r"(1 + grp) : "memory");
}

__global__ __launch_bounds__(256, 4) void fft_kernel(const float* __restrict__ x,
                                                     const float* __restrict__ alpha_raw,
                                                     const float* __restrict__ beta_raw,
                                                     const int* __restrict__ ks) {
    __shared__ float2 tile[HH * SROWC];
    __shared__ float2 tw[64], py[64];
    __shared__ float sh_par[6];
    __shared__ int sh_k;

    int tid = threadIdx.x;
    int plane = blockIdx.x;
    int b = plane >> 9;
    int c = plane & (DI - 1);
    int grp = (tid >> 5) & 1;   // even/odd warp -> lines [0,32) / [32,64)

    if (tid < 64) {
        float ang = 6.283185307179586f * (float)tid / 64.f;
        tw[tid] = make_float2(cosf(ang), sinf(ang));
        int kr = ((tid & 7) << 3) | (tid >> 3);   // storage index -> frequency
        float e = 2.f * cosf(6.283185307179586f * (float)kr / 64.f) - 2.f;
        float dtg = g_dtg[b * DI + c];
        float arg = dtg * e;
        py[tid] = make_float2(cosf(arg), sinf(arg));
    }
    if (tid == 0) {
        int k = ks[0]; if (k < 1) k = 1;
        sh_k = k;
        float dt = 1.f / (float)k;
        float al = 0.25f * tanhf(alpha_raw[c]);
        float br = beta_raw[c];
        float sp = (br > 20.f) ? br : log1pf(expf(br));
        float a = 2.f * al;
        float b2 = 2.f * (sp + 1e-4f);
        sh_par[0] = a;
        sh_par[1] = b2;
        sh_par[2] = expf(-a * 0.5f * dt);
        sh_par[3] = 0.5f * dt;
        sh_par[4] = expf(-a * dt);
        sh_par[5] = dt;
    }
    __syncthreads();

    float a = sh_par[0], b2 = sh_par[1];
    float ea_h = sh_par[2], hdt = sh_par[3];
    float ea_f = sh_par[4], fdt = sh_par[5];
    int ksteps = sh_k;
    int azero = fabsf(a) < 1e-6f;

    const float* xp = x + (size_t)b * NTOK * DI + c;
    __nv_bfloat16* bHr = g_Ath + ((size_t)b * 1024 + c) * NTOK;        // hi real (k=c)
    __nv_bfloat16* bHi = g_Ath + ((size_t)b * 1024 + DI + c) * NTOK;   // hi imag (k=512+c)
    __nv_bfloat16* bLr = g_Atl + ((size_t)b * 1024 + c) * NTOK;
    __nv_bfloat16* bLi = g_Atl + ((size_t)b * 1024 + DI + c) * NTOK;

#define FORALL(body)                         \
    {                                        \
        _Pragma("unroll")                    \
        for (int it = 0; it < 2; it++) {     \
            int t = tid + it * 256;          \
            int ln = t & 63, g = t >> 6;     \
            (void)ln; (void)g;               \
            body;                            \
        }                                    \
    }

    for (int step = 0; step < ksteps; step++) {
        if (step == 0) {
            FORALL((pass8x<-1, true, 8, 1, 2, 0>(tile, tw, ln * SROWC, 1, g, ln,
                                                 a, b2, ea_h, hdt, azero, py, xp,
                                                 bHr, bHi, bLr, bLi)));
        } else {
            FORALL((pass8x<-1, true, 8, 1, 1, 0>(tile, tw, ln * SROWC, 1, g, ln,
                                                 a, b2, ea_f, fdt, azero, py, xp,
                                                 bHr, bHi, bLr, bLi)));
        }
        half_bar(grp);
        FORALL((pass8x<-1, false, 1, 8, 0, 0>(tile, tw, ln * SROWC, 1, g, 0,
                                              0.f, 0.f, 0.f, 0.f, 0, py, xp,
                                              bHr, bHi, bLr, bLi)));   // fwd rows s2
        __syncthreads();
        FORALL((pass8x<-1, true, 8, 1, 0, 0>(tile, tw, ln, SROWC, g, 0,
                                             0.f, 0.f, 0.f, 0.f, 0, py, xp,
                                             bHr, bHi, bLr, bLi)));    // fwd cols s1
        half_bar(grp);
        FORALL((pass8x<-1, false, 1, 8, 0, 1>(tile, tw, ln, SROWC, g, ln,
                                              0.f, 0.f, 0.f, 0.f, 0, py, xp,
                                              bHr, bHi, bLr, bLi)));   // fwd cols s2 + phase
        __syncthreads();
        FORALL((pass8x<1, true, 1, 8, 0, 0>(tile, tw, ln * SROWC, 1, g, 0,
                                            0.f, 0.f, 0.f, 0.f, 0, py, xp,
                                            bHr, bHi, bLr, bLi)));     // inv rows s1
        half_bar(grp);
        FORALL((pass8x<1, false, 8, 1, 0, 0>(tile, tw, ln * SROWC, 1, g, 0,
                                             0.f, 0.f, 0.f, 0.f, 0, py, xp,
                                             bHr, bHi, bLr, bLi)));    // inv rows s2
        __syncthreads();
        FORALL((pass8x<1, true, 1, 8, 0, 0>(tile, tw, ln, SROWC, g, 0,
                                            0.f, 0.f, 0.f, 0.f, 0, py, xp,
                                            bHr, bHi, bLr, bLi)));     // inv cols s1
        half_bar(grp);
        if (step == ksteps - 1) {
            FORALL((pass8x<1, false, 8, 1, 0, 3>(tile, tw, ln, SROWC, g, ln,
                                                 a, b2, ea_h, hdt, azero, py, xp,
                                                 bHr, bHi, bLr, bLi)));
        } else {
            FORALL((pass8x<1, false, 8, 1, 0, 0>(tile, tw, ln, SROWC, g, 0,
                                                 0.f, 0.f, 0.f, 0.f, 0, py, xp,
                                                 bHr, bHi, bLr, bLi)));
            __syncthreads();
        }
    }
#undef FORALL
}

// ---------------- Wout fp32 -> bf16 hi/lo -----------------------------------------
__global__ void wconv_kernel(const float* __restrict__ Wout) {
    int i = blockIdx.x * blockDim.x + threadIdx.x;
    if (i < DI * 2 * DI) {
        float v = Wout[i];
        __nv_bfloat16 h = __float2bfloat16(v);
        g_Wh[i] = h;
        g_Wl[i] = __float2bfloat16(v - __bfloat162float(h));
    }
}

// ================= mma.sync bf16 GEMM (R10 config: 128x64 tile, 2 CTA/SM) =========
#define BK 64
#define AH_OFF 0
#define AL_OFF 16384
#define WH_OFF 32768
#define WL_OFF 40960
#define STAGE_B 49152

__device__ __forceinline__ uint32_t smem_u32(const void* p) {
    uint32_t a;
    asm("{ .reg .u64 t; cvta.to.shared.u64 t, %1; cvt.u32.u64 %0, t; }" : "=r"(a) : "l"(p));
    return a;
}
__device__ __forceinline__ void cp16(uint32_t dst, const void* src) {
    asm volatile("cp.async.cg.shared.global [%0], [%1], 16;" :: "r"(dst), "l"(src));
}
__device__ __forceinline__ void ldsm4(uint32_t* r, uint32_t addr) {
    asm volatile("ldmatrix.sync.aligned.m8n8.x4.shared.b16 {%0,%1,%2,%3}, [%4];"
                 : "=r"(r[0]), "=r"(r[1]), "=r"(r[2]), "=r"(r[3]) : "r"(addr));
}
__device__ __forceinline__ void ldsm4t(uint32_t* r, uint32_t addr) {
    asm volatile("ldmatrix.sync.aligned.m8n8.x4.trans.shared.b16 {%0,%1,%2,%3}, [%4];"
                 : "=r"(r[0]), "=r"(r[1]), "=r"(r[2]), "=r"(r[3]) : "r"(addr));
}
__device__ __forceinline__ void mma16816(float* c, const uint32_t* a, uint32_t b0, uint32_t b1) {
    asm volatile("mma.sync.aligned.m16n8k16.row.col.f32.bf16.bf16.f32 "
                 "{%0,%1,%2,%3}, {%4,%5,%6,%7}, {%8,%9}, {%0,%1,%2,%3};"
                 : "+f"(c[0]), "+f"(c[1]), "+f"(c[2]), "+f"(c[3])
                 : "r"(a[0]), "r"(a[1]), "r"(a[2]), "r"(a[3]), "r"(b0), "r"(b1));
}
__device__ __forceinline__ uint32_t swz(uint32_t off) { return off ^ ((off >> 3) & 0x70); }

__global__ __launch_bounds__(256) void mma_gemm_kernel(const float* __restrict__ x,
                                                       const float* __restrict__ Dp,
                                                       float* __restrict__ out) {
    extern __shared__ char dsmem_raw[];
    uint32_t raw = smem_u32(dsmem_raw);
    uint32_t base = (raw + 1023u) & ~1023u;

    int tid = threadIdx.x;
    int wid = tid >> 5, lid = tid & 31;
    int wm = wid >> 1, wn = wid & 1;          // warp grid 4 (M/n) x 2 (N/o)
    int n0 = blockIdx.x * 128;
    int o0 = blockIdx.y * 64;
    int b = blockIdx.z;

    const __nv_bfloat16* gAh = g_Ath + (size_t)b * 1024 * NTOK + n0;   // [k][n], + n0
    const __nv_bfloat16* gAl = g_Atl + (size_t)b * 1024 * NTOK + n0;
    const __nv_bfloat16* gWh = g_Wh + (size_t)o0 * 1024;
    const __nv_bfloat16* gWl = g_Wl + (size_t)o0 * 1024;

    // A loader: [k=64 rows][128 n] = 64 x 256B; 4 threads/row, 4 x 16B per thread
    int rowA = tid >> 2, q4 = tid & 3;
    // W loader: [o=64 rows][64 k] = 64 x 128B; 4 threads/row, 2 x 16B per thread
    int rw = tid >> 2, qw = tid & 3;

#define ISSUE_CHUNK(kc0, stg)                                                              \
    {                                                                                      \
        uint32_t sb = base + (uint32_t)(stg) * STAGE_B;                                    \
        _Pragma("unroll")                                                                  \
        for (int i = 0; i < 4; i++) {                                                      \
            int n16 = q4 + i * 4;                                                          \
            uint32_t so = (uint32_t)(rowA * 256 + ((n16 ^ (rowA & 7)) * 16));              \
            cp16(sb + AH_OFF + so, gAh + (size_t)((kc0) + rowA) * NTOK + n16 * 8);         \
            cp16(sb + AL_OFF + so, gAl + (size_t)((kc0) + rowA) * NTOK + n16 * 8);         \
        }                                                                                  \
        _Pragma("unroll")                                                                  \
        for (int i = 0; i < 2; i++) {                                                      \
            int c16 = qw * 2 + i;                                                          \
            uint32_t so = swz((uint32_t)(rw * 128 + c16 * 16));                            \
            cp16(sb + WH_OFF + so, gWh + (size_t)rw * 1024 + (kc0) + c16 * 8);             \
            cp16(sb + WL_OFF + so, gWl + (size_t)rw * 1024 + (kc0) + c16 * 8);             \
        }                                                                                  \
        asm volatile("cp.async.commit_group;");                                            \
    }

    float acc[2][4][4];
#pragma unroll
    for (int m = 0; m < 2; m++)
#pragma unroll
        for (int nf = 0; nf < 4; nf++)
#pragma unroll
            for (int r = 0; r < 4; r++) acc[m][nf][r] = 0.f;

    ISSUE_CHUNK(0, 0);
    asm volatile("cp.async.wait_group 0;" ::: "memory");
    __syncthreads();

    int sub = lid >> 3, l7 = lid & 7;
    // A fragment (trans) addressing
    int aklane = (sub >> 1) * 8 + l7;
    // W fragment addressing (row-major [o][k], non-trans)
    int wrow_b = wn * 32 + (sub >> 1) * 8 + l7;
    int wkb_b = (sub & 1) * 16;

    for (int ch = 0; ch < 16; ch++) {
        int stg = ch & 1;
        if (ch + 1 < 16) ISSUE_CHUNK((ch + 1) * BK, stg ^ 1);

        uint32_t sb = base + (uint32_t)stg * STAGE_B;
#pragma unroll
        for (int kk = 0; kk < 4; kk++) {
            uint32_t ah[2][4], al[2][4], wh[2][4], wl[2][4];
#pragma unroll
            for (int m = 0; m < 2; m++) {
                int n16 = (wm * 32 + m * 16 + (sub & 1) * 8) >> 3;
                uint32_t off = (uint32_t)((kk * 16 + aklane) * 256 + ((n16 ^ l7) * 16));
                ldsm4t(ah[m], sb + AH_OFF + off);
                ldsm4t(al[m], sb + AL_OFF + off);
            }
#pragma unroll
            for (int np = 0; np < 2; np++) {
                uint32_t off = swz((uint32_t)((wrow_b + np * 16) * 128 + kk * 32 + wkb_b));
                ldsm4(wh[np], sb + WH_OFF + off);
                ldsm4(wl[np], sb + WL_OFF + off);
            }
#pragma unroll
            for (int m = 0; m < 2; m++)
#pragma unroll
                for (int nf = 0; nf < 4; nf++) {
                    uint32_t bh0 = wh[nf >> 1][(nf & 1) * 2], bh1 = wh[nf >> 1][(nf & 1) * 2 + 1];
                    uint32_t bl0 = wl[nf >> 1][(nf & 1) * 2], bl1 = wl[nf >> 1][(nf & 1) * 2 + 1];
                    mma16816(acc[m][nf], ah[m], bh0, bh1);
                    mma16816(acc[m][nf], ah[m], bl0, bl1);
                    mma16816(acc[m][nf], al[m], bh0, bh1);
                }
        }

        if (ch + 1 < 16) {
            asm volatile("cp.async.wait_group 0;" ::: "memory");
            __syncthreads();
        }
    }
#undef ISSUE_CHUNK

    // epilogue: out = acc + x * Dp
    int g = lid >> 2, tg = lid & 3;
    float2 dv[4];
#pragma unroll
    for (int nf = 0; nf < 4; nf++)
        dv[nf] = *(const float2*)(Dp + o0 + wn * 32 + nf * 8 + tg * 2);
#pragma unroll
    for (int m = 0; m < 2; m++)
#pragma unroll
        for (int rr = 0; rr < 2; rr++) {
            int row = n0 + wm * 32 + m * 16 + g + rr * 8;
            size_t rowoff = ((size_t)b * NTOK + row) * DI;
#pragma unroll
            for (int nf = 0; nf < 4; nf++) {
                int col = o0 + wn * 32 + nf * 8 + tg * 2;
                const float2 xv = *(const float2*)(x + rowoff + col);
                float2 ov;
                ov.x = acc[m][nf][rr * 2 + 0] + xv.x * dv[nf].x;
                ov.y = acc[m][nf][rr * 2 + 1] + xv.y * dv[nf].y;
                *(float2*)(out + rowoff + col) = ov;
            }
        }
}

// ---------------- launch ----------------------------------------------------------
extern "C" void kernel_launch(void* const* d_in, const int* in_sizes, int n_in,
                              void* d_out, int out_size) {
    const float* x         = (const float*)d_in[0];
    const float* Wg        = (const float*)d_in[1];
    const float* bg        = (const float*)d_in[2];
    const float* log_base  = (const float*)d_in[3];
    const float* alpha_raw = (const float*)d_in[4];
    const float* beta_raw  = (const float*)d_in[5];
    const float* Wout      = (const float*)d_in[6];
    const float* Dp        = (const float*)d_in[7];
    const int*   ks        = (const int*)d_in[8];
    float* out = (float*)d_out;

    int dyn = 2 * STAGE_B + 1024;
    cudaFuncSetAttribute(mma_gemm_kernel, cudaFuncAttributeMaxDynamicSharedMemorySize, dyn);

    pooled_partial_kernel<<<dim3(BATCH, 16), DI>>>(x);
    pooled_combine_kernel<<<BATCH, DI>>>();
    gamma_kernel<<<dim3(BATCH, 64), 256>>>(Wg, bg, log_base, ks);
    wconv_kernel<<<(DI * 2 * DI + 255) / 256, 256>>>(Wout);
    fft_kernel<<<BATCH * DI, 256>>>(x, alpha_raw, beta_raw, ks);
    mma_gemm_kernel<<<dim3(NTOK / 128, DI / 64, BATCH), 256, dyn>>>(x, Dp, out);
}